// round 16
// baseline (speedup 1.0000x reference)
#include <cuda_runtime.h>
#include <cuda_fp16.h>
#include <cstdint>

// ============================================================================
// BilinearDiscriminator: out = sigmoid( (x @ W^T) @ y^T )
//   x: [16384, 128] f32, y: [16384, 128] f32, W: [128, 128] f32
//   out: [16384, 16384] f32
//
// R16 = R15 resubmitted verbatim after a broker infra failure (no signal).
// Phase-overlap attack: R12 vs R13 showed the GEMM is NOT L1-bound:
// per-SMSP pipe audit gives HMMA 4096 + MUFU 2048 + STG/LDSM/LDG ~4K cyc
// per wave, and observed elapsed ~10K = the SUM (serialized phases, 2 CTA/SM).
// Fix: 64x128 CTA tile, 4 warps (warp tile 32x64 = validated R9 mapping),
// 48KB smem, ~110 regs -> 4 CTAs/SM. Staggered CTAs overlap load/MMA/epilogue
// across disjoint pipes -> elapsed moves toward max(pipe) ~= tensor floor.
// Prep (R12): fused x-transform (split-K, pre-scaled 0.5) + y fp16 convert.
// Epilogue: sigmoid = fma(tanh.approx(s), 0.5, 0.5) on pre-scaled scores.
// ============================================================================

#define NROWS 16384
#define DDIM  128

static __device__ __align__(16) __half g_A[NROWS * DDIM];
static __device__ __align__(16) __half g_B[NROWS * DDIM];

// ---------------------------------------------------------------------------
// Fused prep kernel (unchanged from R12).
// ---------------------------------------------------------------------------
__global__ void __launch_bounds__(256, 2)
prep_kernel(const float* __restrict__ x, const float* __restrict__ y,
            const float* __restrict__ W, int xblocks, int total2) {
    __shared__ float4 Xs[32][32];       // 32 rows x 128 floats
    __shared__ float  red[2][256];

    if ((int)blockIdx.x < xblocks) {
        const int tid  = threadIdx.x;
        const int d    = tid & 127;
        const int half = tid >> 7;
        const int rowbase = blockIdx.x * 32;

        const float4* xv = reinterpret_cast<const float4*>(x) + (size_t)rowbase * 32;
        for (int i = tid; i < 32 * 32; i += 256)
            Xs[i >> 5][i & 31] = xv[i];

        float4 w[16];
        const float4* Wv = reinterpret_cast<const float4*>(W) + d * 32 + half * 16;
#pragma unroll
        for (int k = 0; k < 16; k++) w[k] = Wv[k];
        __syncthreads();

#pragma unroll 1
        for (int r = 0; r < 32; r += 2) {
            const float4* xa = &Xs[r][half * 16];
            const float4* xb = &Xs[r + 1][half * 16];
            float a0 = 0.f, a1 = 0.f, a2 = 0.f, a3 = 0.f;
            float b0 = 0.f, b1 = 0.f, b2 = 0.f, b3 = 0.f;
#pragma unroll
            for (int k = 0; k < 16; k++) {
                float4 va = xa[k];
                float4 vb = xb[k];
                a0 += w[k].x * va.x; a1 += w[k].y * va.y;
                a2 += w[k].z * va.z; a3 += w[k].w * va.w;
                b0 += w[k].x * vb.x; b1 += w[k].y * vb.y;
                b2 += w[k].z * vb.z; b3 += w[k].w * vb.w;
            }
            red[0][tid] = (a0 + a1) + (a2 + a3);
            red[1][tid] = (b0 + b1) + (b2 + b3);
            __syncthreads();
            if (tid < 128) {
                float sa = red[0][tid] + red[0][tid + 128];
                float sb = red[1][tid] + red[1][tid + 128];
                // pre-scale by 0.5: folds sigmoid's s*0.5 into the GEMM operand
                g_A[(size_t)(rowbase + r) * 128 + tid]     = __float2half(0.5f * sa);
                g_A[(size_t)(rowbase + r + 1) * 128 + tid] = __float2half(0.5f * sb);
            }
            __syncthreads();
        }
    } else {
        const int yb = blockIdx.x - xblocks;
        const int stride = 128 * 256;
        for (int i = yb * 256 + threadIdx.x; i < total2; i += stride) {
            float2 v = reinterpret_cast<const float2*>(y)[i];
            reinterpret_cast<__half2*>(g_B)[i] = __floats2half2_rn(v.x, v.y);
        }
    }
}

// ---------------------------------------------------------------------------
// GEMM + sigmoid via mma.sync m16n8k16 fp16, K=128.
//   CTA tile: 64(M) x 128(N). 4 warps: warp_m = wid&1 (32 rows each),
//   warp_n = wid>>1 (64 cols each) -> warp tile 32x64 (R9's validated map).
//   SMEM: A 64 rows + B 128 rows, 256B/row, chunk swizzle c ^= row&7.
//   4 CTAs/SM (48KB smem, ~110 regs): staggered phases overlap pipes.
// ---------------------------------------------------------------------------
static constexpr int SMEM_A_SIZE = 64 * 256;                 // 16 KB
static constexpr int SMEM_B_SIZE = 128 * 256;                // 32 KB
static constexpr int SMEM_TOTAL  = SMEM_A_SIZE + SMEM_B_SIZE; // 48 KB

__device__ __forceinline__ uint32_t smem_u32(const void* p) {
    uint32_t a;
    asm("{ .reg .u64 t; cvta.to.shared.u64 t, %1; cvt.u32.u64 %0, t; }"
        : "=r"(a) : "l"(p));
    return a;
}

__device__ __forceinline__ void ldsm_x4(uint32_t addr, uint32_t& d0, uint32_t& d1,
                                        uint32_t& d2, uint32_t& d3) {
    asm volatile("ldmatrix.sync.aligned.m8n8.x4.shared.b16 {%0,%1,%2,%3}, [%4];"
                 : "=r"(d0), "=r"(d1), "=r"(d2), "=r"(d3) : "r"(addr));
}

__device__ __forceinline__ void mma_16816(float& c0, float& c1, float& c2, float& c3,
                                          uint32_t a0, uint32_t a1, uint32_t a2, uint32_t a3,
                                          uint32_t b0, uint32_t b1) {
    asm volatile("mma.sync.aligned.m16n8k16.row.col.f32.f16.f16.f32 "
                 "{%0,%1,%2,%3}, {%4,%5,%6,%7}, {%8,%9}, {%0,%1,%2,%3};"
                 : "+f"(c0), "+f"(c1), "+f"(c2), "+f"(c3)
                 : "r"(a0), "r"(a1), "r"(a2), "r"(a3), "r"(b0), "r"(b1));
}

// s is PRE-SCALED (score/2): sigmoid = 0.5*tanh(s) + 0.5, one MUFU + one FMA.
__device__ __forceinline__ float sigmoid_prescaled(float s) {
    float t;
    asm("tanh.approx.f32 %0, %1;" : "=f"(t) : "f"(s));
    return fmaf(t, 0.5f, 0.5f);
}

__global__ void __launch_bounds__(128, 4)
gemm_sigmoid_kernel(float* __restrict__ out, int mtot) {
    extern __shared__ char smem[];
    const uint32_t sA = smem_u32(smem);
    const uint32_t sB = sA + SMEM_A_SIZE;
    const int tid = threadIdx.x;
    const int wid = tid >> 5;
    const int lid = tid & 31;
    const int warp_m = wid & 1;    // 2 warps along M, 32 rows each
    const int warp_n = wid >> 1;   // 2 warps along N, 64 cols each

    const int arowbase = blockIdx.y * 64;    // output rows  (x rows)
    const int browbase = blockIdx.x * 128;   // output cols  (y rows)

    // ---- Fill SMEM: A 64 rows, B 128 rows; 16 chunks of 16B per row ----
    const uint4* gA = reinterpret_cast<const uint4*>(g_A) + (size_t)arowbase * 16;
    const uint4* gB = reinterpret_cast<const uint4*>(g_B) + (size_t)browbase * 16;
#pragma unroll
    for (int idx = tid; idx < 1024; idx += 128) {
        int row = idx >> 4;
        int c   = idx & 15;
        uint32_t off = (uint32_t)row * 256u + (uint32_t)((c ^ (row & 7)) << 4);
        *reinterpret_cast<uint4*>(smem + off) = gA[idx];
    }
#pragma unroll
    for (int idx = tid; idx < 2048; idx += 128) {
        int row = idx >> 4;
        int c   = idx & 15;
        uint32_t off = (uint32_t)row * 256u + (uint32_t)((c ^ (row & 7)) << 4);
        *reinterpret_cast<uint4*>(smem + SMEM_A_SIZE + off) = gB[idx];
    }
    __syncthreads();

    // ---- Mainloop: K=128 = 8 k-steps of 16 ----
    float acc[2][8][4];
#pragma unroll
    for (int i = 0; i < 2; i++)
#pragma unroll
        for (int j = 0; j < 8; j++)
#pragma unroll
            for (int q = 0; q < 4; q++) acc[i][j][q] = 0.f;

    const int lane_lo = lid & 15;   // row within 16-row ldmatrix block
    const int lane_hi = lid >> 4;   // 0/1: 16B chunk-half select

    const int a_row0 = warp_m * 32 + lane_lo;        // + i*16
    const int b_row0 = warp_n * 64 + lane_lo;        // + jb*16

#pragma unroll
    for (int q = 0; q < 8; q++) {
        const int ch = q * 2 + lane_hi;              // chunk 0..15

        uint32_t a[2][4];
#pragma unroll
        for (int i = 0; i < 2; i++) {
            int row = a_row0 + i * 16;
            ldsm_x4(sA + (uint32_t)row * 256u + (uint32_t)((ch ^ (row & 7)) << 4),
                    a[i][0], a[i][1], a[i][2], a[i][3]);
        }

        uint32_t b[4][4];
#pragma unroll
        for (int jb = 0; jb < 4; jb++) {
            int row = b_row0 + jb * 16;
            ldsm_x4(sB + (uint32_t)row * 256u + (uint32_t)((ch ^ (row & 7)) << 4),
                    b[jb][0], b[jb][1], b[jb][2], b[jb][3]);
        }

#pragma unroll
        for (int i = 0; i < 2; i++)
#pragma unroll
            for (int j = 0; j < 8; j++) {
                int jb = j >> 1, sel = j & 1;
                mma_16816(acc[i][j][0], acc[i][j][1], acc[i][j][2], acc[i][j][3],
                          a[i][0], a[i][1], a[i][2], a[i][3],
                          b[jb][sel], b[jb][sel + 2]);
            }
    }

    // ---- Epilogue: sigmoid (tanh.approx, pre-scaled) + float2 stores ----
    const int r_base = arowbase + warp_m * 32 + (lid >> 2);
    const int c_base = browbase + warp_n * 64 + ((lid & 3) << 1);
#pragma unroll
    for (int i = 0; i < 2; i++) {
        const int r0 = r_base + i * 16;
        float* p0 = out + (size_t)r0 * mtot + c_base;
        float* p1 = out + (size_t)(r0 + 8) * mtot + c_base;
#pragma unroll
        for (int j = 0; j < 8; j++) {
            float2 v0, v1;
            v0.x = sigmoid_prescaled(acc[i][j][0]);
            v0.y = sigmoid_prescaled(acc[i][j][1]);
            v1.x = sigmoid_prescaled(acc[i][j][2]);
            v1.y = sigmoid_prescaled(acc[i][j][3]);
            *reinterpret_cast<float2*>(p0 + j * 8) = v0;
            *reinterpret_cast<float2*>(p1 + j * 8) = v1;
        }
    }
}

// ---------------------------------------------------------------------------
// kernel_launch
// ---------------------------------------------------------------------------
extern "C" void kernel_launch(void* const* d_in, const int* in_sizes, int n_in,
                              void* d_out, int out_size) {
    const float* x = (const float*)d_in[0];   // [N, 128]
    const float* y = (const float*)d_in[1];   // [M, 128]
    const float* W = (const float*)d_in[2];   // [128, 128]
    float* out = (float*)d_out;

    const int N = in_sizes[0] / DDIM;   // 16384
    const int M = in_sizes[1] / DDIM;   // 16384

    cudaFuncSetAttribute(gemm_sigmoid_kernel,
                         cudaFuncAttributeMaxDynamicSharedMemorySize, SMEM_TOTAL);

    const int xblocks = N / 32;                 // 512
    const int yblocks = 128;
    prep_kernel<<<xblocks + yblocks, 256>>>(x, y, W, xblocks, in_sizes[1] / 2);

    dim3 grid(M / 128, N / 64);
    gemm_sigmoid_kernel<<<grid, 128, SMEM_TOTAL>>>(out, M);
}

// round 17
// speedup vs baseline: 1.3695x; 1.3695x over previous
#include <cuda_runtime.h>
#include <cuda_fp16.h>
#include <cstdint>

// ============================================================================
// BilinearDiscriminator: out = sigmoid( (x @ W^T) @ y^T )
//   x: [16384, 128] f32, y: [16384, 128] f32, W: [128, 128] f32
//   out: [16384, 16384] f32
//
// R17 = R12 config (best measured: 128x128 CTA, 8 warps 32x64, 2 CTA/SM,
// 16 warps/SM) with the tile fill converted to cp.async.cg (16B), removing
// the LDG->RF->STS double-pass from L1. Evidence: {R12,R13,R16} triple shows
// GEMM time tracks L1 bytes/output when >=16 warps/SM (24B->308us, 30B->363us)
// with a latency floor at 8 warps/SM. cp.async cuts 24 -> ~20 B/output.
// Prep (R12): fused x-transform (split-K, pre-scaled 0.5) + y fp16 convert.
// Epilogue: sigmoid = fma(tanh.approx(s), 0.5, 0.5) on pre-scaled scores.
// ============================================================================

#define NROWS 16384
#define DDIM  128

static __device__ __align__(16) __half g_A[NROWS * DDIM];
static __device__ __align__(16) __half g_B[NROWS * DDIM];

// ---------------------------------------------------------------------------
// Fused prep kernel (unchanged from R12).
// ---------------------------------------------------------------------------
__global__ void __launch_bounds__(256, 2)
prep_kernel(const float* __restrict__ x, const float* __restrict__ y,
            const float* __restrict__ W, int xblocks, int total2) {
    __shared__ float4 Xs[32][32];       // 32 rows x 128 floats
    __shared__ float  red[2][256];

    if ((int)blockIdx.x < xblocks) {
        const int tid  = threadIdx.x;
        const int d    = tid & 127;
        const int half = tid >> 7;
        const int rowbase = blockIdx.x * 32;

        const float4* xv = reinterpret_cast<const float4*>(x) + (size_t)rowbase * 32;
        for (int i = tid; i < 32 * 32; i += 256)
            Xs[i >> 5][i & 31] = xv[i];

        float4 w[16];
        const float4* Wv = reinterpret_cast<const float4*>(W) + d * 32 + half * 16;
#pragma unroll
        for (int k = 0; k < 16; k++) w[k] = Wv[k];
        __syncthreads();

#pragma unroll 1
        for (int r = 0; r < 32; r += 2) {
            const float4* xa = &Xs[r][half * 16];
            const float4* xb = &Xs[r + 1][half * 16];
            float a0 = 0.f, a1 = 0.f, a2 = 0.f, a3 = 0.f;
            float b0 = 0.f, b1 = 0.f, b2 = 0.f, b3 = 0.f;
#pragma unroll
            for (int k = 0; k < 16; k++) {
                float4 va = xa[k];
                float4 vb = xb[k];
                a0 += w[k].x * va.x; a1 += w[k].y * va.y;
                a2 += w[k].z * va.z; a3 += w[k].w * va.w;
                b0 += w[k].x * vb.x; b1 += w[k].y * vb.y;
                b2 += w[k].z * vb.z; b3 += w[k].w * vb.w;
            }
            red[0][tid] = (a0 + a1) + (a2 + a3);
            red[1][tid] = (b0 + b1) + (b2 + b3);
            __syncthreads();
            if (tid < 128) {
                float sa = red[0][tid] + red[0][tid + 128];
                float sb = red[1][tid] + red[1][tid + 128];
                // pre-scale by 0.5: folds sigmoid's s*0.5 into the GEMM operand
                g_A[(size_t)(rowbase + r) * 128 + tid]     = __float2half(0.5f * sa);
                g_A[(size_t)(rowbase + r + 1) * 128 + tid] = __float2half(0.5f * sb);
            }
            __syncthreads();
        }
    } else {
        const int yb = blockIdx.x - xblocks;
        const int stride = 128 * 256;
        for (int i = yb * 256 + threadIdx.x; i < total2; i += stride) {
            float2 v = reinterpret_cast<const float2*>(y)[i];
            reinterpret_cast<__half2*>(g_B)[i] = __floats2half2_rn(v.x, v.y);
        }
    }
}

// ---------------------------------------------------------------------------
// GEMM + sigmoid via mma.sync m16n8k16 fp16, K=128.
//   CTA tile: 128(M) x 128(N). 8 warps: warp_m = wid&3 (32 rows),
//   warp_n = wid>>2 (64 cols) -> warp tile 32x64 (validated R9/R12 mapping).
//   SMEM per operand: 128 rows x 256B (16 x 16B chunks), chunk swizzle
//   phys_c = c ^ (row & 7) -> conflict-free cp.async dst and ldmatrix phases.
//   Fill via cp.async.cg (16B): global read bypasses L1, no RF round-trip.
//   2 CTAs/SM: load/epilogue of one CTA overlaps MMA of the other.
// ---------------------------------------------------------------------------
static constexpr int SMEM_TILE  = 128 * 256;       // 32 KB per operand
static constexpr int SMEM_TOTAL = 2 * SMEM_TILE;   // 64 KB

__device__ __forceinline__ uint32_t smem_u32(const void* p) {
    uint32_t a;
    asm("{ .reg .u64 t; cvta.to.shared.u64 t, %1; cvt.u32.u64 %0, t; }"
        : "=r"(a) : "l"(p));
    return a;
}

__device__ __forceinline__ void cp_async16(uint32_t smem_addr, const void* gptr) {
    asm volatile("cp.async.cg.shared.global [%0], [%1], 16;"
                 :: "r"(smem_addr), "l"(gptr));
}

__device__ __forceinline__ void ldsm_x4(uint32_t addr, uint32_t& d0, uint32_t& d1,
                                        uint32_t& d2, uint32_t& d3) {
    asm volatile("ldmatrix.sync.aligned.m8n8.x4.shared.b16 {%0,%1,%2,%3}, [%4];"
                 : "=r"(d0), "=r"(d1), "=r"(d2), "=r"(d3) : "r"(addr));
}

__device__ __forceinline__ void mma_16816(float& c0, float& c1, float& c2, float& c3,
                                          uint32_t a0, uint32_t a1, uint32_t a2, uint32_t a3,
                                          uint32_t b0, uint32_t b1) {
    asm volatile("mma.sync.aligned.m16n8k16.row.col.f32.f16.f16.f32 "
                 "{%0,%1,%2,%3}, {%4,%5,%6,%7}, {%8,%9}, {%0,%1,%2,%3};"
                 : "+f"(c0), "+f"(c1), "+f"(c2), "+f"(c3)
                 : "r"(a0), "r"(a1), "r"(a2), "r"(a3), "r"(b0), "r"(b1));
}

// s is PRE-SCALED (score/2): sigmoid = 0.5*tanh(s) + 0.5, one MUFU + one FMA.
__device__ __forceinline__ float sigmoid_prescaled(float s) {
    float t;
    asm("tanh.approx.f32 %0, %1;" : "=f"(t) : "f"(s));
    return fmaf(t, 0.5f, 0.5f);
}

__global__ void __launch_bounds__(256, 2)
gemm_sigmoid_kernel(float* __restrict__ out, int mtot) {
    extern __shared__ char smem[];
    const uint32_t sA = smem_u32(smem);
    const uint32_t sB = sA + SMEM_TILE;
    const int tid = threadIdx.x;
    const int wid = tid >> 5;
    const int lid = tid & 31;
    const int warp_m = wid & 3;    // 4 warps along M, 32 rows each
    const int warp_n = wid >> 2;   // 2 warps along N, 64 cols each

    const int arowbase = blockIdx.y * 128;   // output rows  (x rows)
    const int browbase = blockIdx.x * 128;   // output cols  (y rows)

    // ---- Fill SMEM via cp.async.cg: 128 rows x 16 chunks of 16B each ----
    const uint4* gA = reinterpret_cast<const uint4*>(g_A) + (size_t)arowbase * 16;
    const uint4* gB = reinterpret_cast<const uint4*>(g_B) + (size_t)browbase * 16;
#pragma unroll
    for (int idx = tid; idx < 2048; idx += 256) {
        int row = idx >> 4;
        int c   = idx & 15;
        uint32_t off = (uint32_t)row * 256u + (uint32_t)((c ^ (row & 7)) << 4);
        cp_async16(sA + off, gA + idx);
        cp_async16(sB + off, gB + idx);
    }
    asm volatile("cp.async.commit_group;");
    asm volatile("cp.async.wait_group 0;" ::: "memory");
    __syncthreads();

    // ---- Mainloop: K=128 = 8 k-steps of 16 ----
    float acc[2][8][4];
#pragma unroll
    for (int i = 0; i < 2; i++)
#pragma unroll
        for (int j = 0; j < 8; j++)
#pragma unroll
            for (int q = 0; q < 4; q++) acc[i][j][q] = 0.f;

    const int lane_lo = lid & 15;   // row within 16-row ldmatrix block
    const int lane_hi = lid >> 4;   // 0/1: 16B chunk-half select

    const int a_row0 = warp_m * 32 + lane_lo;        // + i*16
    const int b_row0 = warp_n * 64 + lane_lo;        // + jb*16

#pragma unroll
    for (int q = 0; q < 8; q++) {
        const int ch = q * 2 + lane_hi;              // chunk 0..15

        uint32_t a[2][4];
#pragma unroll
        for (int i = 0; i < 2; i++) {
            int row = a_row0 + i * 16;
            ldsm_x4(sA + (uint32_t)row * 256u + (uint32_t)((ch ^ (row & 7)) << 4),
                    a[i][0], a[i][1], a[i][2], a[i][3]);
        }

        uint32_t b[4][4];
#pragma unroll
        for (int jb = 0; jb < 4; jb++) {
            int row = b_row0 + jb * 16;
            ldsm_x4(sB + (uint32_t)row * 256u + (uint32_t)((ch ^ (row & 7)) << 4),
                    b[jb][0], b[jb][1], b[jb][2], b[jb][3]);
        }

#pragma unroll
        for (int i = 0; i < 2; i++)
#pragma unroll
            for (int j = 0; j < 8; j++) {
                int jb = j >> 1, sel = j & 1;
                mma_16816(acc[i][j][0], acc[i][j][1], acc[i][j][2], acc[i][j][3],
                          a[i][0], a[i][1], a[i][2], a[i][3],
                          b[jb][sel], b[jb][sel + 2]);
            }
    }

    // ---- Epilogue: sigmoid (tanh.approx, pre-scaled) + float2 stores ----
    const int r_base = arowbase + warp_m * 32 + (lid >> 2);
    const int c_base = browbase + warp_n * 64 + ((lid & 3) << 1);
#pragma unroll
    for (int i = 0; i < 2; i++) {
        const int r0 = r_base + i * 16;
        float* p0 = out + (size_t)r0 * mtot + c_base;
        float* p1 = out + (size_t)(r0 + 8) * mtot + c_base;
#pragma unroll
        for (int j = 0; j < 8; j++) {
            float2 v0, v1;
            v0.x = sigmoid_prescaled(acc[i][j][0]);
            v0.y = sigmoid_prescaled(acc[i][j][1]);
            v1.x = sigmoid_prescaled(acc[i][j][2]);
            v1.y = sigmoid_prescaled(acc[i][j][3]);
            *reinterpret_cast<float2*>(p0 + j * 8) = v0;
            *reinterpret_cast<float2*>(p1 + j * 8) = v1;
        }
    }
}

// ---------------------------------------------------------------------------
// kernel_launch
// ---------------------------------------------------------------------------
extern "C" void kernel_launch(void* const* d_in, const int* in_sizes, int n_in,
                              void* d_out, int out_size) {
    const float* x = (const float*)d_in[0];   // [N, 128]
    const float* y = (const float*)d_in[1];   // [M, 128]
    const float* W = (const float*)d_in[2];   // [128, 128]
    float* out = (float*)d_out;

    const int N = in_sizes[0] / DDIM;   // 16384
    const int M = in_sizes[1] / DDIM;   // 16384

    cudaFuncSetAttribute(gemm_sigmoid_kernel,
                         cudaFuncAttributeMaxDynamicSharedMemorySize, SMEM_TOTAL);

    const int xblocks = N / 32;                 // 512
    const int yblocks = 128;
    prep_kernel<<<xblocks + yblocks, 256>>>(x, y, W, xblocks, in_sizes[1] / 2);

    dim3 grid(M / 128, N / 128);
    gemm_sigmoid_kernel<<<grid, 256, SMEM_TOTAL>>>(out, M);
}